// round 13
// baseline (speedup 1.0000x reference)
#include <cuda_runtime.h>
#include <stdint.h>

// RT-DETR post-processing, GB300 sm_103a — single fused kernel.
// d_in[0]: pred_logits  float32 [256, 1000, 80]
// d_in[1]: pred_boxes   float32 [256, 1000, 4]   (cx, cy, w, h)
// d_in[2]: target_sizes float32 [256, 2]         (img_h, img_w)
// Output float32 concat: [scores 256*300 | labels 256*300 | boxes 256*300*4]

#define NB   256
#define NQ   1000
#define TOPK 300
typedef unsigned long long ull;

__device__ ull g_keys[NB * NQ];
__device__ unsigned g_arrive[NB];   // +16 per row per launch; (old&15)==15 -> last
                                    // (accumulates across graph replays, no reset)

// ---------------------------------------------------------------------------
// Bitonic: sort 32 keys descending across lanes (15 stages).
// ---------------------------------------------------------------------------
__device__ __forceinline__ void shfl_sort32(ull& v, unsigned i) {
    #pragma unroll
    for (unsigned k = 2; k <= 32; k <<= 1) {
        #pragma unroll
        for (int j = 16; j >= 1; j >>= 1) {
            if ((unsigned)j < k) {
                ull pv = __shfl_xor_sync(0xffffffffu, v, j);
                bool keep_max = (((i & k) == 0) == ((i & (unsigned)j) == 0));
                v = keep_max ? (v > pv ? v : pv) : (v < pv ? v : pv);
            }
        }
    }
}

// ---------------------------------------------------------------------------
// Merge-path rank select (descending; keys unique via embedded query id).
// ---------------------------------------------------------------------------
__device__ __forceinline__ ull
rank_select(const ull* __restrict__ A, const ull* __restrict__ B,
            int r, int NA, int NBL) {
    int lo = r + 1 - NBL; if (lo < 0) lo = 0;
    int hi = r + 1;       if (hi > NA) hi = NA;
    while (lo < hi) {
        int i = (lo + hi) >> 1;
        if (B[r - i] > A[i]) hi = i; else lo = i + 1;
    }
    int is = lo, js = r + 1 - lo;
    ull ka = is ? A[is - 1] : 0xFFFFFFFFFFFFFFFFull;
    ull kb = js ? B[js - 1] : 0xFFFFFFFFFFFFFFFFull;
    return ka < kb ? ka : kb;
}

// ---------------------------------------------------------------------------
// Fused kernel. grid = (16, NB), block = 256.
// Phase A (all blocks): score+argmax for 64 queries (8/warp, smem transpose,
//   exact packed tie-break), write keys to g_keys.
// Phase B (16th-arriving block of each row): full row topk — 32 warp-sorted
//   32-runs, 5-level merge-path tree, epilogue. Overlaps with Phase A of
//   other rows; no second launch, keys L2-hot.
// ---------------------------------------------------------------------------
__global__ void __launch_bounds__(256) fused_kernel(const float* __restrict__ logits,
                                                    const float* __restrict__ boxes,
                                                    const float* __restrict__ tsz,
                                                    float* __restrict__ out) {
    __shared__ __align__(16) ull smem[2560];      // 20480 B, dual-purpose
    __shared__ unsigned s_old;
    float4 (*sh)[160] = reinterpret_cast<float4 (*)[160]>(smem);

    int tid  = threadIdx.x;
    int wid  = tid >> 5;
    int lane = tid & 31;
    int b    = blockIdx.y;
    int qb   = blockIdx.x * 64 + wid * 8;          // nominal first query
    int q0   = (qb + 8 > NQ) ? (NQ - 8) : qb;      // clamped (dup work, no write)

    // ---------------- Phase A: score ----------------
    {
        const float4* p = (const float4*)logits + ((size_t)b * NQ + q0) * 20 + lane;
        float4 a0 = p[0], a1 = p[32], a2 = p[64], a3 = p[96], a4 = p[128];
        sh[wid][lane      ] = a0;
        sh[wid][lane +  32] = a1;
        sh[wid][lane +  64] = a2;
        sh[wid][lane +  96] = a3;
        sh[wid][lane + 128] = a4;
        __syncwarp();

        int g = lane >> 2, j = lane & 3;
        const float4* q = &sh[wid][g * 20 + j];
        float4 w0 = q[0], w1 = q[4], w2 = q[8], w3 = q[12], w4 = q[16];

        float m = fmaxf(fmaxf(fmaxf(fmaxf(fmaxf(w0.x, w0.y), fmaxf(w0.z, w0.w)),
                                    fmaxf(fmaxf(w1.x, w1.y), fmaxf(w1.z, w1.w))),
                              fmaxf(fmaxf(fmaxf(w2.x, w2.y), fmaxf(w2.z, w2.w)),
                                    fmaxf(fmaxf(w3.x, w3.y), fmaxf(w3.z, w3.w)))),
                        fmaxf(fmaxf(w4.x, w4.y), fmaxf(w4.z, w4.w)));

        // Per-lane lowest class among maxima; class of elem e of chunk i = 4j+16i+e.
        int cls = 0;
        {
            int cb = 4 * j;
            if (w4.w == m) cls = cb + 64 + 3;
            if (w4.z == m) cls = cb + 64 + 2;
            if (w4.y == m) cls = cb + 64 + 1;
            if (w4.x == m) cls = cb + 64;
            if (w3.w == m) cls = cb + 48 + 3;
            if (w3.z == m) cls = cb + 48 + 2;
            if (w3.y == m) cls = cb + 48 + 1;
            if (w3.x == m) cls = cb + 48;
            if (w2.w == m) cls = cb + 32 + 3;
            if (w2.z == m) cls = cb + 32 + 2;
            if (w2.y == m) cls = cb + 32 + 1;
            if (w2.x == m) cls = cb + 32;
            if (w1.w == m) cls = cb + 16 + 3;
            if (w1.z == m) cls = cb + 16 + 2;
            if (w1.y == m) cls = cb + 16 + 1;
            if (w1.x == m) cls = cb + 16;
            if (w0.w == m) cls = cb + 3;
            if (w0.z == m) cls = cb + 2;
            if (w0.y == m) cls = cb + 1;
            if (w0.x == m) cls = cb;
        }

        unsigned t  = __float_as_uint(m);
        unsigned u0 = t ^ ((unsigned)((int)t >> 31) | 0x80000000u);
        ull pk = ((ull)u0 << 7) | (unsigned)(127 - cls);
        { ull o = __shfl_xor_sync(0xffffffffu, pk, 1); pk = pk > o ? pk : o; }
        { ull o = __shfl_xor_sync(0xffffffffu, pk, 2); pk = pk > o ? pk : o; }

        if (j == 0) {
            int slot = qb + g;                 // unclamped: >=NQ means duplicate
            if (slot < NQ) {
                int qq = q0 + g;
                g_keys[b * NQ + qq] = ((ull)(pk >> 7) << 32)
                                    | ((unsigned)(1023 - qq) << 8)
                                    | (unsigned)(127 - (int)(pk & 0x7f));
            }
        }
    }

    // Publish keys; elect the last-arriving block of this row.
    __threadfence();
    __syncthreads();
    if (tid == 0) s_old = atomicAdd(&g_arrive[b], 1u);
    __syncthreads();
    if ((s_old & 15u) != 15u) return;          // not last: done
    __threadfence();                            // acquire peers' g_keys writes

    // ---------------- Phase B: row topk (last block only) ----------------
    ull* BUF0 = smem;                           // 1024
    ull* BUF1 = smem + 1024;                    // 1024 (16 KB of the 20 KB)

    // 32 sorted 32-runs: warp w sorts runs 4w..4w+3.
    #pragma unroll
    for (int s = 0; s < 4; s++) {
        int e = (wid * 4 + s) * 32 + lane;
        ull v = (e < NQ) ? g_keys[b * NQ + e] : 0ull;
        shfl_sort32(v, (unsigned)lane);
        BUF0[e] = v;
    }
    __syncthreads();

    // L1: 16 merges (32,32) -> 64
    #pragma unroll
    for (int t = tid; t < 1024; t += 256) {
        int pair = t >> 6, r = t & 63;
        const ull* A = BUF0 + pair * 64;
        BUF1[t] = rank_select(A, A + 32, r, 32, 32);
    }
    __syncthreads();

    // L2: 8 merges (64,64) -> 128
    #pragma unroll
    for (int t = tid; t < 1024; t += 256) {
        int pair = t >> 7, r = t & 127;
        const ull* A = BUF1 + pair * 128;
        BUF0[t] = rank_select(A, A + 64, r, 64, 64);
    }
    __syncthreads();

    // L3: 4 merges (128,128) -> 256
    #pragma unroll
    for (int t = tid; t < 1024; t += 256) {
        int pair = t >> 8, r = t & 255;
        const ull* A = BUF0 + pair * 256;
        BUF1[t] = rank_select(A, A + 128, r, 128, 128);
    }
    __syncthreads();

    // L4: 2 merges (256,256) -> top 300 each
    for (int t = tid; t < 2 * TOPK; t += 256) {
        int pair = t / TOPK, r = t - pair * TOPK;
        const ull* A = BUF1 + pair * 512;
        BUF0[pair * TOPK + r] = rank_select(A, A + 256, r, 256, 256);
    }
    __syncthreads();

    // L5: final (300,300) -> rank r, then epilogue.
    for (int r = tid; r < TOPK; r += 256) {
        ull key = rank_select(BUF0, BUF0 + TOPK, r, TOPK, TOPK);

        unsigned u = (unsigned)(key >> 32);
        float logit = (u & 0x80000000u) ? __uint_as_float(u ^ 0x80000000u)
                                        : __uint_as_float(~u);
        float score = 1.0f / (1.0f + expf(-logit));
        bool  valid = (score > 0.05f);

        unsigned lw = (unsigned)(key & 0xffffffffu);
        int qi    = 1023 - (int)((lw >> 8) & 0x3ffu);
        int label = (int)(lw & 0xffu);

        float4 bx = ((const float4*)boxes)[b * NQ + qi];
        float img_h = tsz[b * 2 + 0];
        float img_w = tsz[b * 2 + 1];
        float x0 = (bx.x - 0.5f * bx.z) * img_w;
        float y0 = (bx.y - 0.5f * bx.w) * img_h;
        float x1 = (bx.x + 0.5f * bx.z) * img_w;
        float y1 = (bx.y + 0.5f * bx.w) * img_h;

        float* out_scores = out;
        float* out_labels = out + NB * TOPK;
        float* out_boxes  = out + 2 * NB * TOPK;

        out_scores[b * TOPK + r] = valid ? score : 0.0f;
        out_labels[b * TOPK + r] = valid ? (float)label : -1.0f;
        float4 ob = valid ? make_float4(x0, y0, x1, y1)
                          : make_float4(0.f, 0.f, 0.f, 0.f);
        ((float4*)out_boxes)[b * TOPK + r] = ob;
    }
}

// ---------------------------------------------------------------------------
extern "C" void kernel_launch(void* const* d_in, const int* in_sizes, int n_in,
                              void* d_out, int out_size) {
    const float* logits = (const float*)d_in[0];
    const float* boxes  = (const float*)d_in[1];
    const float* tsz    = (const float*)d_in[2];
    float* out = (float*)d_out;

    dim3 grid(16, NB);                     // 16 blocks x 64 queries per row
    fused_kernel<<<grid, 256>>>(logits, boxes, tsz, out);
}

// round 14
// speedup vs baseline: 1.5475x; 1.5475x over previous
#include <cuda_runtime.h>
#include <stdint.h>

// RT-DETR post-processing, GB300 sm_103a.
// d_in[0]: pred_logits  float32 [256, 1000, 80]
// d_in[1]: pred_boxes   float32 [256, 1000, 4]   (cx, cy, w, h)
// d_in[2]: target_sizes float32 [256, 2]         (img_h, img_w)
// Output float32 concat: [scores 256*300 | labels 256*300 | boxes 256*300*4]

#define NB   256
#define NQ   1000
#define TOPK 300
typedef unsigned long long ull;

__device__ ull g_keys[NB * NQ];

// ---------------------------------------------------------------------------
// Kernel 1: 8 queries per warp. 5 coalesced LDG.128, per-chunk reduction in
// registers, 8-byte packed-key smem transpose (padded, conflict-free), then
// 4 scalar max + 2 shuffles per query. Exact (max value, min class).
// ---------------------------------------------------------------------------
__global__ void __launch_bounds__(256) score_kernel(const float* __restrict__ logits) {
    __shared__ ull sh[8][168];             // 8 warps x (160 chunks + pad)
    int wid  = threadIdx.x >> 5;
    int lane = threadIdx.x & 31;
    int b    = blockIdx.y;
    int q0   = blockIdx.x * 64 + wid * 8;
    if (q0 >= NQ) return;                  // tail warps of last block

    const float4* p = (const float4*)logits + ((size_t)b * NQ + q0) * 20 + lane;
    // Front-batched loads: all 5 LDG.128 in flight.
    float4 a0 = p[0], a1 = p[32], a2 = p[64], a3 = p[96], a4 = p[128];

    // Per-chunk: max of 4, lowest-class among ties, pack (u<<7)|(127-cls).
    // chunk k = lane + 32*s belongs to query k/20, classes 4*(k%20)+e.
    #pragma unroll
    for (int s = 0; s < 5; s++) {
        float4 a = (s == 0) ? a0 : (s == 1) ? a1 : (s == 2) ? a2 : (s == 3) ? a3 : a4;
        int k = lane + 32 * s;
        int d = k / 20;                    // owning query (warp-local)
        float m = fmaxf(fmaxf(a.x, a.y), fmaxf(a.z, a.w));
        int e = (a.x == m) ? 0 : (a.y == m) ? 1 : (a.z == m) ? 2 : 3;  // lowest first
        int cls = 4 * (k - 20 * d) + e;
        unsigned t = __float_as_uint(m);
        unsigned u = t ^ ((unsigned)((int)t >> 31) | 0x80000000u);     // order-preserving
        sh[wid][k + d] = ((ull)u << 7) | (unsigned)(127 - cls);        // padded addr
    }
    __syncwarp();

    // Group-of-4 lanes per query: lane 4g+j reads chunks g*20 + j + 4i.
    int g = lane >> 2, j = lane & 3;
    const ull* r = &sh[wid][21 * g + j];   // addr = (g*20 + j + 4i) + g
    ull pk = r[0];
    { ull o = r[4];  pk = pk > o ? pk : o; }
    { ull o = r[8];  pk = pk > o ? pk : o; }
    { ull o = r[12]; pk = pk > o ? pk : o; }
    { ull o = r[16]; pk = pk > o ? pk : o; }
    { ull o = __shfl_xor_sync(0xffffffffu, pk, 1); pk = pk > o ? pk : o; }
    { ull o = __shfl_xor_sync(0xffffffffu, pk, 2); pk = pk > o ? pk : o; }

    if (j == 0) {                          // lanes 0,4,..,28 -> coalesced STG.64
        int qq = q0 + g;
        g_keys[b * NQ + qq] = ((ull)(unsigned)(pk >> 7) << 32)
                            | ((unsigned)(1023 - qq) << 8)
                            | (unsigned)(127 - (int)(pk & 0x7f));
    }
}

// ---------------------------------------------------------------------------
// Bitonic helpers (descending over index space).
// ---------------------------------------------------------------------------
__device__ __forceinline__ void shfl_merge(ull& v, unsigned i, unsigned k) {
    #pragma unroll
    for (int j = 16; j >= 1; j >>= 1) {
        ull pv = __shfl_xor_sync(0xffffffffu, v, j);
        bool keep_max = (((i & k) == 0) == ((i & (unsigned)j) == 0));
        v = keep_max ? (v > pv ? v : pv) : (v < pv ? v : pv);
    }
}
__device__ __forceinline__ void shfl_sort32(ull& v, unsigned i) {
    #pragma unroll
    for (unsigned k = 2; k <= 32; k <<= 1) {
        #pragma unroll
        for (int j = 16; j >= 1; j >>= 1) {
            if ((unsigned)j < k) {
                ull pv = __shfl_xor_sync(0xffffffffu, v, j);
                bool keep_max = (((i & k) == 0) == ((i & (unsigned)j) == 0));
                v = keep_max ? (v > pv ? v : pv) : (v < pv ? v : pv);
            }
        }
    }
}

// ---------------------------------------------------------------------------
// Merge-path rank select (descending; keys unique via embedded query id).
// ---------------------------------------------------------------------------
__device__ __forceinline__ ull
rank_select(const ull* __restrict__ A, const ull* __restrict__ B,
            int r, int NA, int NBL) {
    int lo = r + 1 - NBL; if (lo < 0) lo = 0;
    int hi = r + 1;       if (hi > NA) hi = NA;
    while (lo < hi) {
        int i = (lo + hi) >> 1;
        if (B[r - i] > A[i]) hi = i; else lo = i + 1;
    }
    int is = lo, js = r + 1 - lo;
    ull ka = is ? A[is - 1] : 0xFFFFFFFFFFFFFFFFull;
    ull kb = js ? B[js - 1] : 0xFFFFFFFFFFFFFFFFull;
    return ka < kb ? ka : kb;
}

// ---------------------------------------------------------------------------
// Kernel 2 (R10 record variant): one block (512 thr) per row. 16 per-warp
// register bitonic 64-sorts (zero barriers), then 4-level merge-path tree
// (5 barriers), then epilogue.
// ---------------------------------------------------------------------------
__global__ void __launch_bounds__(512) topk_kernel(const float* __restrict__ boxes,
                                                   const float* __restrict__ tsz,
                                                   float* __restrict__ out) {
    __shared__ ull BUF0[1024];
    __shared__ ull BUF1[1024];
    int b    = blockIdx.x;
    int tid  = threadIdx.x;
    int wid  = tid >> 5;
    int lane = tid & 31;

    // Per-warp 64-sort: warp w owns keys [w*64, w*64+64).
    {
        int e0 = wid * 64 + lane, e1 = e0 + 32;
        ull v0 = (e0 < NQ) ? g_keys[b * NQ + e0] : 0ull;
        ull v1 = (e1 < NQ) ? g_keys[b * NQ + e1] : 0ull;
        unsigned i0 = (unsigned)lane, i1 = (unsigned)lane + 32;
        shfl_sort32(v0, i0);
        shfl_sort32(v1, i1);
        { ull mx = v0 > v1 ? v0 : v1; v1 = v0 > v1 ? v1 : v0; v0 = mx; } // k=64, j=32
        shfl_merge(v0, i0, 64);
        shfl_merge(v1, i1, 64);
        BUF0[wid * 64 + lane]      = v0;
        BUF0[wid * 64 + lane + 32] = v1;
    }
    __syncthreads();

    // L1: 8 merges (64,64) -> BUF1
    #pragma unroll
    for (int t = tid; t < 1024; t += 512) {
        int pair = t >> 7, r = t & 127;
        const ull* A = BUF0 + pair * 128;
        BUF1[t] = rank_select(A, A + 64, r, 64, 64);
    }
    __syncthreads();

    // L2: 4 merges (128,128) -> BUF0
    #pragma unroll
    for (int t = tid; t < 1024; t += 512) {
        int pair = t >> 8, r = t & 255;
        const ull* A = BUF1 + pair * 256;
        BUF0[t] = rank_select(A, A + 128, r, 128, 128);
    }
    __syncthreads();

    // L3: 2 merges (256,256) -> top 300 each -> BUF1
    for (int t = tid; t < 2 * TOPK; t += 512) {
        int pair = t / TOPK, r = t - pair * TOPK;
        const ull* A = BUF0 + pair * 512;
        BUF1[pair * TOPK + r] = rank_select(A, A + 256, r, 256, 256);
    }
    __syncthreads();

    // L4: final (300,300) -> rank tid, then epilogue.
    if (tid < TOPK) {
        ull key = rank_select(BUF1, BUF1 + TOPK, tid, TOPK, TOPK);

        unsigned u = (unsigned)(key >> 32);
        float logit = (u & 0x80000000u) ? __uint_as_float(u ^ 0x80000000u)
                                        : __uint_as_float(~u);
        float score = 1.0f / (1.0f + expf(-logit));
        bool  valid = (score > 0.05f);

        unsigned lw = (unsigned)(key & 0xffffffffu);
        int qi    = 1023 - (int)((lw >> 8) & 0x3ffu);
        int label = (int)(lw & 0xffu);

        float4 bx = ((const float4*)boxes)[b * NQ + qi];
        float img_h = tsz[b * 2 + 0];
        float img_w = tsz[b * 2 + 1];
        float x0 = (bx.x - 0.5f * bx.z) * img_w;
        float y0 = (bx.y - 0.5f * bx.w) * img_h;
        float x1 = (bx.x + 0.5f * bx.z) * img_w;
        float y1 = (bx.y + 0.5f * bx.w) * img_h;

        float* out_scores = out;
        float* out_labels = out + NB * TOPK;
        float* out_boxes  = out + 2 * NB * TOPK;

        out_scores[b * TOPK + tid] = valid ? score : 0.0f;
        out_labels[b * TOPK + tid] = valid ? (float)label : -1.0f;
        float4 ob = valid ? make_float4(x0, y0, x1, y1)
                          : make_float4(0.f, 0.f, 0.f, 0.f);
        ((float4*)out_boxes)[b * TOPK + tid] = ob;
    }
}

// ---------------------------------------------------------------------------
extern "C" void kernel_launch(void* const* d_in, const int* in_sizes, int n_in,
                              void* d_out, int out_size) {
    const float* logits = (const float*)d_in[0];
    const float* boxes  = (const float*)d_in[1];
    const float* tsz    = (const float*)d_in[2];
    float* out = (float*)d_out;

    dim3 sgrid(16, NB);                    // 16 blocks x 64 queries per row
    score_kernel<<<sgrid, 256>>>(logits);
    topk_kernel<<<NB, 512>>>(boxes, tsz, out);
}

// round 15
// speedup vs baseline: 1.5560x; 1.0055x over previous
#include <cuda_runtime.h>
#include <stdint.h>

// RT-DETR post-processing, GB300 sm_103a — PDL-overlapped 2-kernel pipeline.
// d_in[0]: pred_logits  float32 [256, 1000, 80]
// d_in[1]: pred_boxes   float32 [256, 1000, 4]   (cx, cy, w, h)
// d_in[2]: target_sizes float32 [256, 2]         (img_h, img_w)
// Output float32 concat: [scores 256*300 | labels 256*300 | boxes 256*300*4]

#define NB   256
#define NQ   1000
#define TOPK 300
typedef unsigned long long ull;

__device__ ull g_keys[NB * NQ];

// ---------------------------------------------------------------------------
// Kernel 1: 8 queries per warp. 5 coalesced LDG.128, per-chunk register
// reduction, 8-byte packed-key smem transpose (padded, conflict-free),
// 4 scalar max + 2 shuffles per query. Exact (max value, min class).
// Triggers programmatic launch completion so topk can overlap.
// ---------------------------------------------------------------------------
__global__ void __launch_bounds__(256) score_kernel(const float* __restrict__ logits) {
    __shared__ ull sh[8][168];             // 8 warps x (160 chunks + pad)
    int wid  = threadIdx.x >> 5;
    int lane = threadIdx.x & 31;
    int b    = blockIdx.y;
    int q0   = blockIdx.x * 64 + wid * 8;
    if (q0 >= NQ) return;                  // tail warps exit (counts as trigger)

    const float4* p = (const float4*)logits + ((size_t)b * NQ + q0) * 20 + lane;
    float4 a0 = p[0], a1 = p[32], a2 = p[64], a3 = p[96], a4 = p[128];

    // Per-chunk: max of 4, lowest class among ties, pack (u<<7)|(127-cls).
    // chunk k = lane + 32*s belongs to query k/20, classes 4*(k%20)+e.
    #pragma unroll
    for (int s = 0; s < 5; s++) {
        float4 a = (s == 0) ? a0 : (s == 1) ? a1 : (s == 2) ? a2 : (s == 3) ? a3 : a4;
        int k = lane + 32 * s;
        int d = k / 20;
        float m = fmaxf(fmaxf(a.x, a.y), fmaxf(a.z, a.w));
        int e = (a.x == m) ? 0 : (a.y == m) ? 1 : (a.z == m) ? 2 : 3;
        int cls = 4 * (k - 20 * d) + e;
        unsigned t = __float_as_uint(m);
        unsigned u = t ^ ((unsigned)((int)t >> 31) | 0x80000000u);
        sh[wid][k + d] = ((ull)u << 7) | (unsigned)(127 - cls);   // padded addr
    }
    __syncwarp();

    // Group-of-4 lanes per query: lane 4g+j reads chunks g*20 + j + 4i.
    int g = lane >> 2, j = lane & 3;
    const ull* r = &sh[wid][21 * g + j];
    ull pk = r[0];
    { ull o = r[4];  pk = pk > o ? pk : o; }
    { ull o = r[8];  pk = pk > o ? pk : o; }
    { ull o = r[12]; pk = pk > o ? pk : o; }
    { ull o = r[16]; pk = pk > o ? pk : o; }
    { ull o = __shfl_xor_sync(0xffffffffu, pk, 1); pk = pk > o ? pk : o; }
    { ull o = __shfl_xor_sync(0xffffffffu, pk, 2); pk = pk > o ? pk : o; }

    if (j == 0) {                          // lanes 0,4,..,28 -> coalesced STG.64
        int qq = q0 + g;
        g_keys[b * NQ + qq] = ((ull)(unsigned)(pk >> 7) << 32)
                            | ((unsigned)(1023 - qq) << 8)
                            | (unsigned)(127 - (int)(pk & 0x7f));
    }

    // Allow the dependent topk launch to proceed (writes above are ordered).
    cudaTriggerProgrammaticLaunchCompletion();
}

// ---------------------------------------------------------------------------
// Bitonic helpers (descending over index space).
// ---------------------------------------------------------------------------
__device__ __forceinline__ void shfl_merge(ull& v, unsigned i, unsigned k) {
    #pragma unroll
    for (int j = 16; j >= 1; j >>= 1) {
        ull pv = __shfl_xor_sync(0xffffffffu, v, j);
        bool keep_max = (((i & k) == 0) == ((i & (unsigned)j) == 0));
        v = keep_max ? (v > pv ? v : pv) : (v < pv ? v : pv);
    }
}
__device__ __forceinline__ void shfl_sort32(ull& v, unsigned i) {
    #pragma unroll
    for (unsigned k = 2; k <= 32; k <<= 1) {
        #pragma unroll
        for (int j = 16; j >= 1; j >>= 1) {
            if ((unsigned)j < k) {
                ull pv = __shfl_xor_sync(0xffffffffu, v, j);
                bool keep_max = (((i & k) == 0) == ((i & (unsigned)j) == 0));
                v = keep_max ? (v > pv ? v : pv) : (v < pv ? v : pv);
            }
        }
    }
}

// ---------------------------------------------------------------------------
// Merge-path rank select (descending; keys unique via embedded query id).
// ---------------------------------------------------------------------------
__device__ __forceinline__ ull
rank_select(const ull* __restrict__ A, const ull* __restrict__ B,
            int r, int NA, int NBL) {
    int lo = r + 1 - NBL; if (lo < 0) lo = 0;
    int hi = r + 1;       if (hi > NA) hi = NA;
    while (lo < hi) {
        int i = (lo + hi) >> 1;
        if (B[r - i] > A[i]) hi = i; else lo = i + 1;
    }
    int is = lo, js = r + 1 - lo;
    ull ka = is ? A[is - 1] : 0xFFFFFFFFFFFFFFFFull;
    ull kb = js ? B[js - 1] : 0xFFFFFFFFFFFFFFFFull;
    return ka < kb ? ka : kb;
}

// ---------------------------------------------------------------------------
// Kernel 2: one block (512 thr) per row. PRE-SYNC: prefetch the row's boxes
// (16 KB) + target size into smem/regs while score still runs. POST-SYNC:
// 16 per-warp 64-sorts, 4-level merge-path tree, epilogue from smem boxes.
// ---------------------------------------------------------------------------
__global__ void __launch_bounds__(512) topk_kernel(const float* __restrict__ boxes,
                                                   const float* __restrict__ tsz,
                                                   float* __restrict__ out) {
    __shared__ ull BUF0[1024];
    __shared__ ull BUF1[1024];
    __shared__ float4 BBOX[NQ];
    int b    = blockIdx.x;
    int tid  = threadIdx.x;
    int wid  = tid >> 5;
    int lane = tid & 31;

    // ---- Pre-sync prologue (overlaps with score_kernel) ----
    float img_h = tsz[b * 2 + 0];
    float img_w = tsz[b * 2 + 1];
    {
        const float4* bp = (const float4*)boxes + b * NQ;
        for (int t = tid; t < NQ; t += 512) BBOX[t] = bp[t];
    }

    // Wait for score_kernel's g_keys to be visible.
    cudaGridDependencySynchronize();

    // Per-warp 64-sort: warp w owns keys [w*64, w*64+64).
    {
        int e0 = wid * 64 + lane, e1 = e0 + 32;
        ull v0 = (e0 < NQ) ? g_keys[b * NQ + e0] : 0ull;
        ull v1 = (e1 < NQ) ? g_keys[b * NQ + e1] : 0ull;
        unsigned i0 = (unsigned)lane, i1 = (unsigned)lane + 32;
        shfl_sort32(v0, i0);
        shfl_sort32(v1, i1);
        { ull mx = v0 > v1 ? v0 : v1; v1 = v0 > v1 ? v1 : v0; v0 = mx; } // k=64,j=32
        shfl_merge(v0, i0, 64);
        shfl_merge(v1, i1, 64);
        BUF0[wid * 64 + lane]      = v0;
        BUF0[wid * 64 + lane + 32] = v1;
    }
    __syncthreads();   // also orders BBOX writes before epilogue reads

    // L1: 8 merges (64,64) -> BUF1
    #pragma unroll
    for (int t = tid; t < 1024; t += 512) {
        int pair = t >> 7, r = t & 127;
        const ull* A = BUF0 + pair * 128;
        BUF1[t] = rank_select(A, A + 64, r, 64, 64);
    }
    __syncthreads();

    // L2: 4 merges (128,128) -> BUF0
    #pragma unroll
    for (int t = tid; t < 1024; t += 512) {
        int pair = t >> 8, r = t & 255;
        const ull* A = BUF1 + pair * 256;
        BUF0[t] = rank_select(A, A + 128, r, 128, 128);
    }
    __syncthreads();

    // L3: 2 merges (256,256) -> top 300 each -> BUF1
    for (int t = tid; t < 2 * TOPK; t += 512) {
        int pair = t / TOPK, r = t - pair * TOPK;
        const ull* A = BUF0 + pair * 512;
        BUF1[pair * TOPK + r] = rank_select(A, A + 256, r, 256, 256);
    }
    __syncthreads();

    // L4: final (300,300) -> rank tid, then epilogue (boxes from smem).
    if (tid < TOPK) {
        ull key = rank_select(BUF1, BUF1 + TOPK, tid, TOPK, TOPK);

        unsigned u = (unsigned)(key >> 32);
        float logit = (u & 0x80000000u) ? __uint_as_float(u ^ 0x80000000u)
                                        : __uint_as_float(~u);
        float score = 1.0f / (1.0f + expf(-logit));
        bool  valid = (score > 0.05f);

        unsigned lw = (unsigned)(key & 0xffffffffu);
        int qi    = 1023 - (int)((lw >> 8) & 0x3ffu);
        int label = (int)(lw & 0xffu);

        float4 bx = BBOX[qi];
        float x0 = (bx.x - 0.5f * bx.z) * img_w;
        float y0 = (bx.y - 0.5f * bx.w) * img_h;
        float x1 = (bx.x + 0.5f * bx.z) * img_w;
        float y1 = (bx.y + 0.5f * bx.w) * img_h;

        float* out_scores = out;
        float* out_labels = out + NB * TOPK;
        float* out_boxes  = out + 2 * NB * TOPK;

        out_scores[b * TOPK + tid] = valid ? score : 0.0f;
        out_labels[b * TOPK + tid] = valid ? (float)label : -1.0f;
        float4 ob = valid ? make_float4(x0, y0, x1, y1)
                          : make_float4(0.f, 0.f, 0.f, 0.f);
        ((float4*)out_boxes)[b * TOPK + tid] = ob;
    }
}

// ---------------------------------------------------------------------------
extern "C" void kernel_launch(void* const* d_in, const int* in_sizes, int n_in,
                              void* d_out, int out_size) {
    const float* logits = (const float*)d_in[0];
    const float* boxes  = (const float*)d_in[1];
    const float* tsz    = (const float*)d_in[2];
    float* out = (float*)d_out;

    dim3 sgrid(16, NB);                    // 16 blocks x 64 queries per row
    score_kernel<<<sgrid, 256>>>(logits);

    // topk with Programmatic Dependent Launch: becomes resident + runs its
    // prologue while score_kernel drains; gated by cudaGridDependencySynchronize.
    cudaLaunchConfig_t cfg = {};
    cfg.gridDim  = dim3(NB);
    cfg.blockDim = dim3(512);
    cfg.dynamicSmemBytes = 0;
    cfg.stream   = 0;
    cudaLaunchAttribute attr[1];
    attr[0].id = cudaLaunchAttributeProgrammaticStreamSerialization;
    attr[0].val.programmaticStreamSerializationAllowed = 1;
    cfg.attrs    = attr;
    cfg.numAttrs = 1;
    cudaLaunchKernelEx(&cfg, topk_kernel, boxes, tsz, out);
}

// round 17
// speedup vs baseline: 1.5647x; 1.0056x over previous
#include <cuda_runtime.h>
#include <stdint.h>

// RT-DETR post-processing, GB300 sm_103a — PDL pipeline, 2 rows per topk block.
// d_in[0]: pred_logits  float32 [256, 1000, 80]
// d_in[1]: pred_boxes   float32 [256, 1000, 4]   (cx, cy, w, h)
// d_in[2]: target_sizes float32 [256, 2]         (img_h, img_w)
// Output float32 concat: [scores 256*300 | labels 256*300 | boxes 256*300*4]

#define NB   256
#define NQ   1000
#define TOPK 300
typedef unsigned long long ull;

__device__ ull g_keys[NB * NQ];

// ---------------------------------------------------------------------------
// Kernel 1: 8 queries per warp. 5 coalesced LDG.128, per-chunk register
// reduction, 8-byte packed-key smem transpose (padded, conflict-free),
// 4 scalar max + 2 shuffles per query. Exact (max value, min class).
// ---------------------------------------------------------------------------
__global__ void __launch_bounds__(256) score_kernel(const float* __restrict__ logits) {
    __shared__ ull sh[8][168];             // 8 warps x (160 chunks + pad)
    int wid  = threadIdx.x >> 5;
    int lane = threadIdx.x & 31;
    int b    = blockIdx.y;
    int q0   = blockIdx.x * 64 + wid * 8;
    if (q0 >= NQ) return;                  // tail warps exit

    const float4* p = (const float4*)logits + ((size_t)b * NQ + q0) * 20 + lane;
    float4 a0 = p[0], a1 = p[32], a2 = p[64], a3 = p[96], a4 = p[128];

    // Per-chunk: max of 4, lowest class among ties, pack (u<<7)|(127-cls).
    // chunk k = lane + 32*s belongs to query k/20, classes 4*(k%20)+e.
    #pragma unroll
    for (int s = 0; s < 5; s++) {
        float4 a = (s == 0) ? a0 : (s == 1) ? a1 : (s == 2) ? a2 : (s == 3) ? a3 : a4;
        int k = lane + 32 * s;
        int d = k / 20;
        float m = fmaxf(fmaxf(a.x, a.y), fmaxf(a.z, a.w));
        int e = (a.x == m) ? 0 : (a.y == m) ? 1 : (a.z == m) ? 2 : 3;
        int cls = 4 * (k - 20 * d) + e;
        unsigned t = __float_as_uint(m);
        unsigned u = t ^ ((unsigned)((int)t >> 31) | 0x80000000u);
        sh[wid][k + d] = ((ull)u << 7) | (unsigned)(127 - cls);   // padded addr
    }
    __syncwarp();

    // Group-of-4 lanes per query: lane 4g+j reads chunks g*20 + j + 4i.
    int g = lane >> 2, j = lane & 3;
    const ull* r = &sh[wid][21 * g + j];
    ull pk = r[0];
    { ull o = r[4];  pk = pk > o ? pk : o; }
    { ull o = r[8];  pk = pk > o ? pk : o; }
    { ull o = r[12]; pk = pk > o ? pk : o; }
    { ull o = r[16]; pk = pk > o ? pk : o; }
    { ull o = __shfl_xor_sync(0xffffffffu, pk, 1); pk = pk > o ? pk : o; }
    { ull o = __shfl_xor_sync(0xffffffffu, pk, 2); pk = pk > o ? pk : o; }

    if (j == 0) {                          // lanes 0,4,..,28 -> coalesced STG.64
        int qq = q0 + g;
        g_keys[b * NQ + qq] = ((ull)(unsigned)(pk >> 7) << 32)
                            | ((unsigned)(1023 - qq) << 8)
                            | (unsigned)(127 - (int)(pk & 0x7f));
    }

    cudaTriggerProgrammaticLaunchCompletion();
}

// ---------------------------------------------------------------------------
// Bitonic helpers (descending over index space).
// ---------------------------------------------------------------------------
__device__ __forceinline__ void shfl_merge(ull& v, unsigned i, unsigned k) {
    #pragma unroll
    for (int j = 16; j >= 1; j >>= 1) {
        ull pv = __shfl_xor_sync(0xffffffffu, v, j);
        bool keep_max = (((i & k) == 0) == ((i & (unsigned)j) == 0));
        v = keep_max ? (v > pv ? v : pv) : (v < pv ? v : pv);
    }
}
__device__ __forceinline__ void shfl_sort32(ull& v, unsigned i) {
    #pragma unroll
    for (unsigned k = 2; k <= 32; k <<= 1) {
        #pragma unroll
        for (int j = 16; j >= 1; j >>= 1) {
            if ((unsigned)j < k) {
                ull pv = __shfl_xor_sync(0xffffffffu, v, j);
                bool keep_max = (((i & k) == 0) == ((i & (unsigned)j) == 0));
                v = keep_max ? (v > pv ? v : pv) : (v < pv ? v : pv);
            }
        }
    }
}

// ---------------------------------------------------------------------------
// Merge-path rank select (descending; keys unique via embedded query id).
// ---------------------------------------------------------------------------
__device__ __forceinline__ ull
rank_select(const ull* __restrict__ A, const ull* __restrict__ B,
            int r, int NA, int NBL) {
    int lo = r + 1 - NBL; if (lo < 0) lo = 0;
    int hi = r + 1;       if (hi > NA) hi = NA;
    while (lo < hi) {
        int i = (lo + hi) >> 1;
        if (B[r - i] > A[i]) hi = i; else lo = i + 1;
    }
    int is = lo, js = r + 1 - lo;
    ull ka = is ? A[is - 1] : 0xFFFFFFFFFFFFFFFFull;
    ull kb = js ? B[js - 1] : 0xFFFFFFFFFFFFFFFFull;
    return ka < kb ? ka : kb;
}

// ---------------------------------------------------------------------------
// Kernel 2: 2 rows per block (grid NB/2, block 1024). Warps 0-15 -> row 2bx,
// warps 16-31 -> row 2bx+1. Per row: 16 per-warp 64-sorts (no barriers),
// 4-level merge-path tree (shared balanced barriers), epilogue.
// Single wave: 128 blocks <= 148 SMs, 8 warps/SMSP keeps issue fed.
// ---------------------------------------------------------------------------
__global__ void __launch_bounds__(1024) topk_kernel(const float* __restrict__ boxes,
                                                    const float* __restrict__ tsz,
                                                    float* __restrict__ out) {
    __shared__ ull BUF0[2][1024];
    __shared__ ull BUF1[2][1024];
    int tid  = threadIdx.x;
    int half = tid >> 9;                   // 0 or 1: which row of the pair
    int tid2 = tid & 511;
    int wid2 = tid2 >> 5;                  // warp within the row (0..15)
    int lane = tid & 31;
    int b    = blockIdx.x * 2 + half;

    ull* B0 = BUF0[half];
    ull* B1 = BUF1[half];

    // Wait for score_kernel's g_keys to be visible (PDL).
    cudaGridDependencySynchronize();

    // Per-warp 64-sort: warp w owns keys [w*64, w*64+64).
    {
        int e0 = wid2 * 64 + lane, e1 = e0 + 32;
        ull v0 = (e0 < NQ) ? g_keys[b * NQ + e0] : 0ull;
        ull v1 = (e1 < NQ) ? g_keys[b * NQ + e1] : 0ull;
        unsigned i0 = (unsigned)lane, i1 = (unsigned)lane + 32;
        shfl_sort32(v0, i0);
        shfl_sort32(v1, i1);
        { ull mx = v0 > v1 ? v0 : v1; v1 = v0 > v1 ? v1 : v0; v0 = mx; } // k=64,j=32
        shfl_merge(v0, i0, 64);
        shfl_merge(v1, i1, 64);
        B0[wid2 * 64 + lane]      = v0;
        B0[wid2 * 64 + lane + 32] = v1;
    }
    __syncthreads();

    // L1: 8 merges (64,64) -> B1
    #pragma unroll
    for (int t = tid2; t < 1024; t += 512) {
        int pair = t >> 7, r = t & 127;
        const ull* A = B0 + pair * 128;
        B1[t] = rank_select(A, A + 64, r, 64, 64);
    }
    __syncthreads();

    // L2: 4 merges (128,128) -> B0
    #pragma unroll
    for (int t = tid2; t < 1024; t += 512) {
        int pair = t >> 8, r = t & 255;
        const ull* A = B1 + pair * 256;
        B0[t] = rank_select(A, A + 128, r, 128, 128);
    }
    __syncthreads();

    // L3: 2 merges (256,256) -> top 300 each -> B1
    for (int t = tid2; t < 2 * TOPK; t += 512) {
        int pair = t / TOPK, r = t - pair * TOPK;
        const ull* A = B0 + pair * 512;
        B1[pair * TOPK + r] = rank_select(A, A + 256, r, 256, 256);
    }
    __syncthreads();

    // L4: final (300,300) -> rank tid2, then epilogue.
    if (tid2 < TOPK) {
        ull key = rank_select(B1, B1 + TOPK, tid2, TOPK, TOPK);

        unsigned u = (unsigned)(key >> 32);
        float logit = (u & 0x80000000u) ? __uint_as_float(u ^ 0x80000000u)
                                        : __uint_as_float(~u);
        float score = 1.0f / (1.0f + expf(-logit));
        bool  valid = (score > 0.05f);

        unsigned lw = (unsigned)(key & 0xffffffffu);
        int qi    = 1023 - (int)((lw >> 8) & 0x3ffu);
        int label = (int)(lw & 0xffu);

        float4 bx = ((const float4*)boxes)[b * NQ + qi];
        float img_h = tsz[b * 2 + 0];
        float img_w = tsz[b * 2 + 1];
        float x0 = (bx.x - 0.5f * bx.z) * img_w;
        float y0 = (bx.y - 0.5f * bx.w) * img_h;
        float x1 = (bx.x + 0.5f * bx.z) * img_w;
        float y1 = (bx.y + 0.5f * bx.w) * img_h;

        float* out_scores = out;
        float* out_labels = out + NB * TOPK;
        float* out_boxes  = out + 2 * NB * TOPK;

        out_scores[b * TOPK + tid2] = valid ? score : 0.0f;
        out_labels[b * TOPK + tid2] = valid ? (float)label : -1.0f;
        float4 ob = valid ? make_float4(x0, y0, x1, y1)
                          : make_float4(0.f, 0.f, 0.f, 0.f);
        ((float4*)out_boxes)[b * TOPK + tid2] = ob;
    }
}

// ---------------------------------------------------------------------------
extern "C" void kernel_launch(void* const* d_in, const int* in_sizes, int n_in,
                              void* d_out, int out_size) {
    const float* logits = (const float*)d_in[0];
    const float* boxes  = (const float*)d_in[1];
    const float* tsz    = (const float*)d_in[2];
    float* out = (float*)d_out;

    dim3 sgrid(16, NB);                    // 16 blocks x 64 queries per row
    score_kernel<<<sgrid, 256>>>(logits);

    // topk with Programmatic Dependent Launch; 2 rows per 1024-thread block.
    cudaLaunchConfig_t cfg = {};
    cfg.gridDim  = dim3(NB / 2);
    cfg.blockDim = dim3(1024);
    cfg.dynamicSmemBytes = 0;
    cfg.stream   = 0;
    cudaLaunchAttribute attr[1];
    attr[0].id = cudaLaunchAttributeProgrammaticStreamSerialization;
    attr[0].val.programmaticStreamSerializationAllowed = 1;
    cfg.attrs    = attr;
    cfg.numAttrs = 1;
    cudaLaunchKernelEx(&cfg, topk_kernel, boxes, tsz, out);
}